// round 11
// baseline (speedup 1.0000x reference)
#include <cuda_runtime.h>
#include <cuda_fp16.h>
#include <cstdint>

#define DEV_INLINE __device__ __forceinline__

constexpr int KTOT = 768;
constexpr int NST = 16, KST = 32;                 // K = 512 in 16 stages of 32
constexpr int SBW = 20;                            // u32 words per B row (16 kt + 4 pad)
constexpr int SAW = 72;                            // u32 words per A k-row (64 m + 8 pad)
constexpr int B_STAGE_BYTES = 512 * SBW * 4;       // 40960
constexpr int A_STAGE_BYTES = 16 * SAW * 4;        // 4608

// static device scratch
__device__ float g_sbias[4 * 512];
__device__ __align__(128) uint32_t g_wst[NST * 512 * SBW];   // fp16-packed W stage images

// ---------------- PTX helpers ----------------

DEV_INLINE uint32_t smem_u32(const void* p) {
    uint32_t a;
    asm("{ .reg .u64 t; cvta.to.shared.u64 t, %1; cvt.u32.u64 %0, t; }" : "=r"(a) : "l"(p));
    return a;
}
DEV_INLINE void mbar_init(uint32_t a, uint32_t cnt) {
    asm volatile("mbarrier.init.shared.b64 [%0], %1;" :: "r"(a), "r"(cnt) : "memory");
}
DEV_INLINE void mbar_arrive(uint32_t a) {
    asm volatile("mbarrier.arrive.release.cta.shared::cta.b64 _, [%0];" :: "r"(a) : "memory");
}
DEV_INLINE void mbar_expect_tx(uint32_t a, uint32_t bytes) {
    asm volatile("mbarrier.arrive.expect_tx.shared.b64 _, [%0], %1;" :: "r"(a), "r"(bytes) : "memory");
}
DEV_INLINE void mbar_wait(uint32_t a, uint32_t parity) {
    asm volatile(
        "{ .reg .pred P;\n"
        "W_%=:\n"
        " mbarrier.try_wait.parity.acquire.cta.shared::cta.b64 P, [%0], %1, 0x989680;\n"
        " @P bra.uni D_%=;\n"
        " bra.uni W_%=;\n"
        "D_%=:\n}"
        :: "r"(a), "r"(parity) : "memory");
}
DEV_INLINE void bulk_g2s(uint32_t dst, const void* src, uint32_t bytes, uint32_t mbar) {
    asm volatile(
        "cp.async.bulk.shared::cluster.global.mbarrier::complete_tx::bytes [%0], [%1], %2, [%3];"
        :: "r"(dst), "l"(src), "r"(bytes), "r"(mbar) : "memory");
}
DEV_INLINE void mma_f16(float* d, const uint32_t* a, uint32_t b0, uint32_t b1) {
    asm volatile(
        "mma.sync.aligned.m16n8k16.row.col.f32.f16.f16.f32 "
        "{%0,%1,%2,%3}, {%4,%5,%6,%7}, {%8,%9}, {%0,%1,%2,%3};\n"
        : "+f"(d[0]), "+f"(d[1]), "+f"(d[2]), "+f"(d[3])
        : "r"(a[0]), "r"(a[1]), "r"(a[2]), "r"(a[3]), "r"(b0), "r"(b1));
}
DEV_INLINE void ldsm_x4(uint32_t& r0, uint32_t& r1, uint32_t& r2, uint32_t& r3, uint32_t addr) {
    asm volatile("ldmatrix.sync.aligned.m8n8.x4.shared.b16 {%0,%1,%2,%3}, [%4];"
                 : "=r"(r0), "=r"(r1), "=r"(r2), "=r"(r3) : "r"(addr));
}
DEV_INLINE uint32_t packh2(float lo, float hi) {
    __half2 h = __floats2half2_rn(lo, hi);
    return *reinterpret_cast<uint32_t*>(&h);
}

// ---------------- merged prologue kernel ----------------
// blocks [0,640): W stage images (16*512*20 words); blocks [640,896): sbias GEMV

__global__ void prep_kernel(const float* __restrict__ s,
                            const float* __restrict__ W,
                            const float* __restrict__ bias) {
    if (blockIdx.x < 640) {
        int idx = blockIdx.x * 256 + threadIdx.x;   // 163840
        if (idx >= NST * 512 * SBW) return;
        int kt = idx % SBW;
        int rest = idx / SBW;
        int n = rest & 511, st = rest >> 9;
        uint32_t v = 0;
        if (kt < 16) {
            const float* p = W + n * KTOT + st * KST + 2 * kt;
            v = packh2(p[0], p[1]);
        }
        g_wst[idx] = v;
    } else {
        int gw = ((blockIdx.x - 640) * 256 + threadIdx.x) >> 5;   // 2048 warps: (b,o)
        int lane = threadIdx.x & 31;
        int b = gw >> 9, o = gw & 511;
        const float* wrow = W + o * KTOT + 512;
        const float* srow = s + b * 256;
        float acc = 0.f;
#pragma unroll
        for (int j = 0; j < 8; ++j) acc += srow[lane + 32 * j] * wrow[lane + 32 * j];
#pragma unroll
        for (int off = 16; off; off >>= 1) acc += __shfl_xor_sync(0xffffffffu, acc, off);
        if (lane == 0) g_sbias[b * 512 + o] = acc + bias[o];
    }
}

// ---------------- fused kernel ----------------
// Grid 1024: CTA = (b,t). Tile 64(m) x 512(n), K=512 in 16 k32 stages.
// 512 threads = 16 warps (2m x 8n). Rings: B 3-deep (tma[3] cnt1, rd[3] cnt16),
// A 8-deep distance-3 (ardy[8] cnt256; A loads done by tid<256).

// smem layout
constexpr int MB_TMA  = 0;                 // 3 x 8B
constexpr int MB_ARDY = 32;                // 8 x 8B
constexpr int MB_RD   = 96;                // 3 x 8B
constexpr int F_RS   = 32;                 // float indices (byte 128)
constexpr int F_RQ   = F_RS + 512;
constexpr int F_MU   = F_RQ + 512;
constexpr int F_RSTD = F_MU + 64;
constexpr int F_LW   = F_RSTD + 64;
constexpr int F_LB   = F_LW + 512;
constexpr int F_SBIA = F_LB + 512;         // ends float 2720 (byte 10880)
constexpr int SM_A   = 11264;              // 8 x 4608 = 36864
constexpr int SM_B   = SM_A + 8 * A_STAGE_BYTES;        // 48128
constexpr int SMEM_BYTES = SM_B + 3 * B_STAGE_BYTES;    // 171008
constexpr int F_STAGE = SM_A >> 2;         // epilogue staging [512 n][68]f over A+B region

__global__ __launch_bounds__(512, 1)
void fused_kernel(const float* __restrict__ x,
                  const float* __restrict__ prelu_a,
                  const float* __restrict__ lnw,
                  const float* __restrict__ lnb,
                  float* __restrict__ out) {
    extern __shared__ float smf[];
    const uint32_t smb = smem_u32(smf);
    const int tid = threadIdx.x;
    const int b = blockIdx.x >> 8;
    const int t = blockIdx.x & 255;

    // epilogue constants
    smf[F_LW + tid]   = lnw[tid];
    smf[F_LB + tid]   = lnb[tid];
    smf[F_SBIA + tid] = g_sbias[b * 512 + tid];

    if (tid == 0) {
#pragma unroll
        for (int i = 0; i < 3; ++i) mbar_init(smb + MB_TMA + 8 * i, 1);
#pragma unroll
        for (int i = 0; i < 8; ++i) mbar_init(smb + MB_ARDY + 8 * i, 256);
#pragma unroll
        for (int i = 0; i < 3; ++i) mbar_init(smb + MB_RD + 8 * i, 16);
    }
    __syncthreads();

    const int lane = tid & 31, w = tid >> 5;
    const int wm = w >> 3, wn = w & 7;
    const int qid = lane >> 2, tig = lane & 3;
    const int akt = (tid >> 4) & 15;     // A k-pair row (tid<256 active)
    const int am0 = (tid & 15) * 4;      // m quad

    const uint32_t b_lane_off =
        (uint32_t)((((lane >> 4) * 8 + (lane & 7)) * SBW + ((lane >> 3) & 1) * 4) * 4);

    const float* xa_base = x + (size_t)b * 512 * 16384 + t * 64 + am0;
    auto ldgA = [&](int s, float4& f0, float4& f1) {
        const float* p = xa_base + (size_t)(s * KST + 2 * akt) * 16384;
        f0 = *(const float4*)p;
        f1 = *(const float4*)(p + 16384);
    };
    auto stsA = [&](int abuf, const float4& f0, const float4& f1) {
        uint32_t w0 = packh2(f0.x, f1.x);
        uint32_t w1 = packh2(f0.y, f1.y);
        uint32_t w2 = packh2(f0.z, f1.z);
        uint32_t w3 = packh2(f0.w, f1.w);
        uint32_t dst = smb + SM_A + abuf * A_STAGE_BYTES + (akt * SAW + am0) * 4;
        asm volatile("st.shared.v4.b32 [%0], {%1,%2,%3,%4};"
                     :: "r"(dst), "r"(w0), "r"(w1), "r"(w2), "r"(w3));
    };

    float acc[2][8][4];
#pragma unroll
    for (int mt = 0; mt < 2; ++mt)
#pragma unroll
        for (int nt = 0; nt < 8; ++nt)
#pragma unroll
            for (int r = 0; r < 4; ++r) acc[mt][nt][r] = 0.f;

    // prologue: A stages 0..2 (tid<256) + B stages 0..2
    if (tid < 256) {
        float4 f0, f1;
#pragma unroll
        for (int i = 0; i < 3; ++i) {
            ldgA(i, f0, f1); stsA(i, f0, f1);
            mbar_arrive(smb + MB_ARDY + 8 * i);
        }
    }
    if (tid == 0) {
#pragma unroll
        for (int i = 0; i < 3; ++i) {
            mbar_expect_tx(smb + MB_TMA + 8 * i, B_STAGE_BYTES);
            bulk_g2s(smb + SM_B + i * B_STAGE_BYTES, g_wst + i * 512 * SBW,
                     B_STAGE_BYTES, smb + MB_TMA + 8 * i);
        }
    }

    float4 pf0, pf1;   // A prefetch registers
    for (int s = 0; s < NST; ++s) {
        const int slot3 = s % 3;
        const uint32_t ph3 = (uint32_t)((s / 3) & 1);
        if (s + 3 < NST && tid < 256) ldgA(s + 3, pf0, pf1);

        mbar_wait(smb + MB_TMA + 8 * slot3, ph3);                       // B(s) full
        mbar_wait(smb + MB_ARDY + 8 * (s & 7), (uint32_t)((s >> 3) & 1)); // A(s) ready

        const uint32_t* A2 = (const uint32_t*)((const char*)smf + SM_A +
                                               (s & 7) * A_STAGE_BYTES);
        const uint32_t bwarp = smb + SM_B + slot3 * B_STAGE_BYTES +
                               (uint32_t)(wn * 64 * SBW * 4) + b_lane_off;

#pragma unroll
        for (int c4 = 0; c4 < 2; ++c4) {
            const int kt0 = c4 * 8;
            uint32_t bb[4][4];
#pragma unroll
            for (int np = 0; np < 4; ++np)
                ldsm_x4(bb[np][0], bb[np][1], bb[np][2], bb[np][3],
                        bwarp + (uint32_t)(np * 16 * SBW * 4 + kt0 * 4));
            uint32_t a[2][4];
#pragma unroll
            for (int mt = 0; mt < 2; ++mt) {
                const int m0 = wm * 32 + mt * 16 + qid;
                a[mt][0] = A2[(kt0 + tig) * SAW + m0];
                a[mt][1] = A2[(kt0 + tig) * SAW + m0 + 8];
                a[mt][2] = A2[(kt0 + 4 + tig) * SAW + m0];
                a[mt][3] = A2[(kt0 + 4 + tig) * SAW + m0 + 8];
            }
#pragma unroll
            for (int np = 0; np < 4; ++np) {
                mma_f16(acc[0][np * 2],     a[0], bb[np][0], bb[np][1]);
                mma_f16(acc[1][np * 2],     a[1], bb[np][0], bb[np][1]);
                mma_f16(acc[0][np * 2 + 1], a[0], bb[np][2], bb[np][3]);
                mma_f16(acc[1][np * 2 + 1], a[1], bb[np][2], bb[np][3]);
            }
        }

        if (lane == 0) mbar_arrive(smb + MB_RD + 8 * slot3);   // this warp done with B(s)

        if (s + 3 < NST) {
            if (tid < 256) {
                stsA((s + 3) & 7, pf0, pf1);
                mbar_arrive(smb + MB_ARDY + 8 * ((s + 3) & 7));
            }
            if (w == s && lane == 0) {   // rotating issuer (s = 0..12)
                mbar_wait(smb + MB_RD + 8 * slot3, ph3);   // all warps read B(s)
                mbar_expect_tx(smb + MB_TMA + 8 * slot3, B_STAGE_BYTES);
                bulk_g2s(smb + SM_B + slot3 * B_STAGE_BYTES,
                         g_wst + (s + 3) * 512 * SBW, B_STAGE_BYTES,
                         smb + MB_TMA + 8 * slot3);
            }
        }
    }

    __syncthreads();   // mainloop done; A+B region becomes epilogue staging

    // ---------------- epilogue ----------------
    const float pa = prelu_a[0];

    float srow[4] = {0.f, 0.f, 0.f, 0.f};
    float qrow[4] = {0.f, 0.f, 0.f, 0.f};
#pragma unroll
    for (int mt = 0; mt < 2; ++mt)
#pragma unroll
        for (int nt = 0; nt < 8; ++nt)
#pragma unroll
            for (int r = 0; r < 4; ++r) {
                const int half = r >> 1;
                const int n = wn * 64 + nt * 8 + tig * 2 + (r & 1);
                const int rrow = wm * 32 + mt * 16 + half * 8 + qid;
                float v = acc[mt][nt][r] + smf[F_SBIA + n];
                v = (v >= 0.f) ? v : pa * v;
                smf[F_STAGE + n * 68 + rrow] = v;   // stride 68: conflict-free
                srow[mt * 2 + half] += v;
                qrow[mt * 2 + half] += v * v;
            }
#pragma unroll
    for (int off = 1; off <= 2; off <<= 1)
#pragma unroll
        for (int i = 0; i < 4; ++i) {
            srow[i] += __shfl_xor_sync(0xffffffffu, srow[i], off);
            qrow[i] += __shfl_xor_sync(0xffffffffu, qrow[i], off);
        }
    if (tig == 0) {
#pragma unroll
        for (int i = 0; i < 4; ++i) {
            const int rrow = wm * 32 + (i >> 1) * 16 + (i & 1) * 8 + qid;
            smf[F_RS + rrow * 8 + wn] = srow[i];
            smf[F_RQ + rrow * 8 + wn] = qrow[i];
        }
    }
    __syncthreads();
    if (tid < 64) {
        float s8 = 0.f, q8 = 0.f;
#pragma unroll
        for (int j = 0; j < 8; ++j) {
            s8 += smf[F_RS + tid * 8 + j];
            q8 += smf[F_RQ + tid * 8 + j];
        }
        const float mu = s8 * (1.f / 512.f);
        float var = q8 * (1.f / 512.f) - mu * mu;
        var = fmaxf(var, 0.f);
        smf[F_MU + tid] = mu;
        smf[F_RSTD + tid] = rsqrtf(var + 1e-8f);
    }
    __syncthreads();

    // Phase 2: float2-vectorized normalize + residual + store. Rows 2*lane, 2*lane+1.
    const int row0 = 2 * lane;
    const float2 mu2 = *(const float2*)&smf[F_MU + row0];
    const float2 rs2 = *(const float2*)&smf[F_RSTD + row0];
    const size_t base = ((size_t)b * 512 * 256 + t) * 64;
#pragma unroll 4
    for (int i = 0; i < 32; ++i) {
        const int n = i * 16 + w;
        const float lw = smf[F_LW + n], lb = smf[F_LB + n];
        const float2 v2 = *(const float2*)&smf[F_STAGE + n * 68 + row0];
        const size_t gi = base + (size_t)n * 16384 + row0;
        const float2 xr = *(const float2*)(x + gi);
        float2 o2;
        o2.x = (v2.x - mu2.x) * rs2.x * lw + lb + xr.x;
        o2.y = (v2.y - mu2.y) * rs2.y * lw + lb + xr.y;
        *(float2*)(out + gi) = o2;
    }
}

// ---------------- launch ----------------

extern "C" void kernel_launch(void* const* d_in, const int* in_sizes, int n_in,
                              void* d_out, int out_size) {
    (void)in_sizes; (void)n_in; (void)out_size;
    const float* x      = (const float*)d_in[0];
    const float* s      = (const float*)d_in[1];
    // d_in[2..4]: prelu1_a, ln1_w, ln1_b — dead code in the reference
    const float* W      = (const float*)d_in[5];
    const float* bias   = (const float*)d_in[6];
    const float* prelu2 = (const float*)d_in[7];
    const float* ln2w   = (const float*)d_in[8];
    const float* ln2b   = (const float*)d_in[9];
    float* out = (float*)d_out;

    cudaFuncSetAttribute(fused_kernel,
                         cudaFuncAttributeMaxDynamicSharedMemorySize, SMEM_BYTES);

    prep_kernel<<<896, 256>>>(s, W, bias);
    fused_kernel<<<1024, 512, SMEM_BYTES>>>(x, prelu2, ln2w, ln2b, out);
}

// round 12
// speedup vs baseline: 1.0712x; 1.0712x over previous
#include <cuda_runtime.h>
#include <cuda_fp16.h>
#include <cstdint>

#define DEV_INLINE __device__ __forceinline__

constexpr int KTOT = 768;
constexpr int NSTAGES = 8, KSTAGE = 64;          // K = 512
constexpr int SBW = 36;                           // u32 words per B row (32 kt + 4 pad)
constexpr int SAW = 72;                           // u32 words per A k-row (64 m + 8 pad)
constexpr int B_STAGE_BYTES = 512 * SBW * 4;      // 73728
constexpr int A_STAGE_BYTES = 32 * SAW * 4;       // 9216

// static device scratch
__device__ float g_sbias[4 * 512];
__device__ __align__(128) uint32_t g_wst[NSTAGES * 512 * SBW];  // fp16-packed, padded W stages

// ---------------- PTX helpers ----------------

DEV_INLINE uint32_t smem_u32(const void* p) {
    uint32_t a;
    asm("{ .reg .u64 t; cvta.to.shared.u64 t, %1; cvt.u32.u64 %0, t; }" : "=r"(a) : "l"(p));
    return a;
}
DEV_INLINE void mbar_init(uint32_t a, uint32_t cnt) {
    asm volatile("mbarrier.init.shared.b64 [%0], %1;" :: "r"(a), "r"(cnt) : "memory");
}
DEV_INLINE void mbar_arrive(uint32_t a) {
    asm volatile("mbarrier.arrive.release.cta.shared::cta.b64 _, [%0];" :: "r"(a) : "memory");
}
DEV_INLINE void mbar_expect_tx(uint32_t a, uint32_t bytes) {
    asm volatile("mbarrier.arrive.expect_tx.shared.b64 _, [%0], %1;" :: "r"(a), "r"(bytes) : "memory");
}
DEV_INLINE void mbar_wait(uint32_t a, uint32_t parity) {
    asm volatile(
        "{ .reg .pred P;\n"
        "W_%=:\n"
        " mbarrier.try_wait.parity.acquire.cta.shared::cta.b64 P, [%0], %1, 0x989680;\n"
        " @P bra.uni D_%=;\n"
        " bra.uni W_%=;\n"
        "D_%=:\n}"
        :: "r"(a), "r"(parity) : "memory");
}
DEV_INLINE void bulk_g2s(uint32_t dst, const void* src, uint32_t bytes, uint32_t mbar) {
    asm volatile(
        "cp.async.bulk.shared::cluster.global.mbarrier::complete_tx::bytes [%0], [%1], %2, [%3];"
        :: "r"(dst), "l"(src), "r"(bytes), "r"(mbar) : "memory");
}
DEV_INLINE void mma_f16(float* d, const uint32_t* a, uint32_t b0, uint32_t b1) {
    asm volatile(
        "mma.sync.aligned.m16n8k16.row.col.f32.f16.f16.f32 "
        "{%0,%1,%2,%3}, {%4,%5,%6,%7}, {%8,%9}, {%0,%1,%2,%3};\n"
        : "+f"(d[0]), "+f"(d[1]), "+f"(d[2]), "+f"(d[3])
        : "r"(a[0]), "r"(a[1]), "r"(a[2]), "r"(a[3]), "r"(b0), "r"(b1));
}
DEV_INLINE void ldsm_x4(uint32_t& r0, uint32_t& r1, uint32_t& r2, uint32_t& r3, uint32_t addr) {
    asm volatile("ldmatrix.sync.aligned.m8n8.x4.shared.b16 {%0,%1,%2,%3}, [%4];"
                 : "=r"(r0), "=r"(r1), "=r"(r2), "=r"(r3) : "r"(addr));
}
DEV_INLINE uint32_t packh2(float lo, float hi) {
    __half2 h = __floats2half2_rn(lo, hi);
    return *reinterpret_cast<uint32_t*>(&h);
}

// ---------------- merged prologue kernel ----------------

__global__ void prep_kernel(const float* __restrict__ s,
                            const float* __restrict__ W,
                            const float* __restrict__ bias) {
    if (blockIdx.x < 576) {
        int idx = blockIdx.x * 256 + threadIdx.x;   // 8*512*36 = 147456
        if (idx >= NSTAGES * 512 * SBW) return;
        int kt = idx % SBW;
        int rest = idx / SBW;
        int n = rest & 511, st = rest >> 9;
        uint32_t v = 0;
        if (kt < 32) {
            const float* p = W + n * KTOT + st * KSTAGE + 2 * kt;
            v = packh2(p[0], p[1]);
        }
        g_wst[idx] = v;
    } else {
        int gw = ((blockIdx.x - 576) * 256 + threadIdx.x) >> 5;   // 2048 warps: (b,o)
        int lane = threadIdx.x & 31;
        int b = gw >> 9, o = gw & 511;
        const float* wrow = W + o * KTOT + 512;
        const float* srow = s + b * 256;
        float acc = 0.f;
#pragma unroll
        for (int j = 0; j < 8; ++j) acc += srow[lane + 32 * j] * wrow[lane + 32 * j];
#pragma unroll
        for (int off = 16; off; off >>= 1) acc += __shfl_xor_sync(0xffffffffu, acc, off);
        if (lane == 0) g_sbias[b * 512 + o] = acc + bias[o];
    }
}

// ---------------- fused kernel ----------------
// Grid 1024: CTA = (b,t). Tile 64(m) x 512(n), K=512 in 8 stages of 64.
// 512 threads = 16 warps (2m x 8n). Barrier-free mainloop: mbarrier ring
// (tma[2] B-full, ardy[4] A-ready cnt512, rd[2] read-done cnt16).

// smem layout (bytes / float indices)
constexpr int MB_TMA  = 0;                 // 2 x 8B
constexpr int MB_ARDY = 16;                // 4 x 8B
constexpr int MB_RD   = 48;                // 2 x 8B
constexpr int F_RS   = 16;                 // float indices (byte 64)
constexpr int F_RQ   = F_RS + 512;
constexpr int F_MU   = F_RQ + 512;
constexpr int F_RSTD = F_MU + 64;
constexpr int F_LW   = F_RSTD + 64;
constexpr int F_LB   = F_LW + 512;
constexpr int F_SBIA = F_LB + 512;         // ends float 2704
constexpr int SM_A   = 12288;              // 4 x 9216 = 36864
constexpr int SM_B   = SM_A + 4 * A_STAGE_BYTES;        // 49152
constexpr int SMEM_BYTES = SM_B + 2 * B_STAGE_BYTES;    // 196608
constexpr int F_STAGE = SM_A >> 2;         // epilogue staging [512 n][68]f over A+B region

__global__ __launch_bounds__(512, 1)
void fused_kernel(const float* __restrict__ x,
                  const float* __restrict__ prelu_a,
                  const float* __restrict__ lnw,
                  const float* __restrict__ lnb,
                  float* __restrict__ out) {
    extern __shared__ float smf[];
    const uint32_t smb = smem_u32(smf);
    const int tid = threadIdx.x;
    const int b = blockIdx.x >> 8;
    const int t = blockIdx.x & 255;

    // epilogue constants
    smf[F_LW + tid]   = lnw[tid];
    smf[F_LB + tid]   = lnb[tid];
    smf[F_SBIA + tid] = g_sbias[b * 512 + tid];

    if (tid == 0) {
        mbar_init(smb + MB_TMA + 0, 1);
        mbar_init(smb + MB_TMA + 8, 1);
#pragma unroll
        for (int i = 0; i < 4; ++i) mbar_init(smb + MB_ARDY + 8 * i, 512);
        mbar_init(smb + MB_RD + 0, 16);
        mbar_init(smb + MB_RD + 8, 16);
    }
    __syncthreads();

    const int lane = tid & 31, w = tid >> 5;
    const int wm = w >> 3, wn = w & 7;
    const int qid = lane >> 2, tig = lane & 3;
    const int akt = tid >> 4;            // 0..31  (k-pair row)
    const int am0 = (tid & 15) * 4;      // m quad

    const uint32_t b_lane_off =
        (uint32_t)((((lane >> 4) * 8 + (lane & 7)) * SBW + ((lane >> 3) & 1) * 4) * 4);

    const float* xa_base = x + (size_t)b * 512 * 16384 + t * 64 + am0;
    auto ldgA = [&](int s, float4& f0, float4& f1) {
        const float* p = xa_base + (size_t)(s * KSTAGE + 2 * akt) * 16384;
        f0 = *(const float4*)p;
        f1 = *(const float4*)(p + 16384);
    };
    auto stsA = [&](int abuf, const float4& f0, const float4& f1) {
        uint32_t w0 = packh2(f0.x, f1.x);
        uint32_t w1 = packh2(f0.y, f1.y);
        uint32_t w2 = packh2(f0.z, f1.z);
        uint32_t w3 = packh2(f0.w, f1.w);
        uint32_t dst = smb + SM_A + abuf * A_STAGE_BYTES + (akt * SAW + am0) * 4;
        asm volatile("st.shared.v4.b32 [%0], {%1,%2,%3,%4};"
                     :: "r"(dst), "r"(w0), "r"(w1), "r"(w2), "r"(w3));
    };

    float acc[2][8][4];
#pragma unroll
    for (int mt = 0; mt < 2; ++mt)
#pragma unroll
        for (int nt = 0; nt < 8; ++nt)
#pragma unroll
            for (int r = 0; r < 4; ++r) acc[mt][nt][r] = 0.f;

    // prologue: A stages 0,1 + B stages 0,1
    {
        float4 f0, f1;
        ldgA(0, f0, f1); stsA(0, f0, f1);
        mbar_arrive(smb + MB_ARDY + 0);
        ldgA(1, f0, f1); stsA(1, f0, f1);
        mbar_arrive(smb + MB_ARDY + 8);
    }
    if (tid == 0) {
        mbar_expect_tx(smb + MB_TMA + 0, B_STAGE_BYTES);
        bulk_g2s(smb + SM_B, g_wst, B_STAGE_BYTES, smb + MB_TMA + 0);
        mbar_expect_tx(smb + MB_TMA + 8, B_STAGE_BYTES);
        bulk_g2s(smb + SM_B + B_STAGE_BYTES, g_wst + 512 * SBW, B_STAGE_BYTES,
                 smb + MB_TMA + 8);
    }

    float4 pf0, pf1;   // A prefetch registers
    for (int s = 0; s < NSTAGES; ++s) {
        const int buf = s & 1;
        const uint32_t par2 = (uint32_t)((s >> 1) & 1);   // tma / rd parity
        if (s + 2 < NSTAGES) ldgA(s + 2, pf0, pf1);

        mbar_wait(smb + MB_TMA + 8 * buf, par2);                       // B(s) full
        mbar_wait(smb + MB_ARDY + 8 * (s & 3), (uint32_t)((s >> 2) & 1)); // A(s) ready

        const uint32_t* A2 = (const uint32_t*)((const char*)smf + SM_A +
                                               (s & 3) * A_STAGE_BYTES);
        const uint32_t bwarp = smb + SM_B + buf * B_STAGE_BYTES +
                               (uint32_t)(wn * 64 * SBW * 4) + b_lane_off;

#pragma unroll
        for (int c4 = 0; c4 < 4; ++c4) {
            const int kt0 = c4 * 8;
            uint32_t bb[4][4];
#pragma unroll
            for (int np = 0; np < 4; ++np)
                ldsm_x4(bb[np][0], bb[np][1], bb[np][2], bb[np][3],
                        bwarp + (uint32_t)(np * 16 * SBW * 4 + kt0 * 4));
            uint32_t a[2][4];
#pragma unroll
            for (int mt = 0; mt < 2; ++mt) {
                const int m0 = wm * 32 + mt * 16 + qid;
                a[mt][0] = A2[(kt0 + tig) * SAW + m0];
                a[mt][1] = A2[(kt0 + tig) * SAW + m0 + 8];
                a[mt][2] = A2[(kt0 + 4 + tig) * SAW + m0];
                a[mt][3] = A2[(kt0 + 4 + tig) * SAW + m0 + 8];
            }
#pragma unroll
            for (int np = 0; np < 4; ++np) {
                mma_f16(acc[0][np * 2],     a[0], bb[np][0], bb[np][1]);
                mma_f16(acc[1][np * 2],     a[1], bb[np][0], bb[np][1]);
                mma_f16(acc[0][np * 2 + 1], a[0], bb[np][2], bb[np][3]);
                mma_f16(acc[1][np * 2 + 1], a[1], bb[np][2], bb[np][3]);
            }
        }

        // reads of A(s)/B(s) complete for this warp
        if (lane == 0) mbar_arrive(smb + MB_RD + 8 * buf);

        if (s + 2 < NSTAGES) {
            stsA((s + 2) & 3, pf0, pf1);
            mbar_arrive(smb + MB_ARDY + 8 * ((s + 2) & 3));
            if (w == s && lane == 0) {   // rotating issuer warp (s = 0..5)
                mbar_wait(smb + MB_RD + 8 * buf, par2);  // all warps read B(s)
                mbar_expect_tx(smb + MB_TMA + 8 * buf, B_STAGE_BYTES);
                bulk_g2s(smb + SM_B + buf * B_STAGE_BYTES,
                         g_wst + (s + 2) * 512 * SBW, B_STAGE_BYTES,
                         smb + MB_TMA + 8 * buf);
            }
        }
    }

    __syncthreads();   // everyone done with mainloop; A+B region becomes staging

    // ---------------- epilogue ----------------
    const float pa = prelu_a[0];

    float srow[4] = {0.f, 0.f, 0.f, 0.f};
    float qrow[4] = {0.f, 0.f, 0.f, 0.f};
#pragma unroll
    for (int mt = 0; mt < 2; ++mt)
#pragma unroll
        for (int nt = 0; nt < 8; ++nt)
#pragma unroll
            for (int r = 0; r < 4; ++r) {
                const int half = r >> 1;
                const int n = wn * 64 + nt * 8 + tig * 2 + (r & 1);
                const int rrow = wm * 32 + mt * 16 + half * 8 + qid;
                float v = acc[mt][nt][r] + smf[F_SBIA + n];
                v = (v >= 0.f) ? v : pa * v;
                smf[F_STAGE + n * 68 + rrow] = v;   // stride 68: banks 8*tig+qid, conflict-free
                srow[mt * 2 + half] += v;
                qrow[mt * 2 + half] += v * v;
            }
#pragma unroll
    for (int off = 1; off <= 2; off <<= 1)
#pragma unroll
        for (int i = 0; i < 4; ++i) {
            srow[i] += __shfl_xor_sync(0xffffffffu, srow[i], off);
            qrow[i] += __shfl_xor_sync(0xffffffffu, qrow[i], off);
        }
    if (tig == 0) {
#pragma unroll
        for (int i = 0; i < 4; ++i) {
            const int rrow = wm * 32 + (i >> 1) * 16 + (i & 1) * 8 + qid;
            smf[F_RS + rrow * 8 + wn] = srow[i];
            smf[F_RQ + rrow * 8 + wn] = qrow[i];
        }
    }
    __syncthreads();
    if (tid < 64) {
        float s8 = 0.f, q8 = 0.f;
#pragma unroll
        for (int j = 0; j < 8; ++j) {
            s8 += smf[F_RS + tid * 8 + j];
            q8 += smf[F_RQ + tid * 8 + j];
        }
        const float mu = s8 * (1.f / 512.f);
        float var = q8 * (1.f / 512.f) - mu * mu;
        var = fmaxf(var, 0.f);
        smf[F_MU + tid] = mu;
        smf[F_RSTD + tid] = rsqrtf(var + 1e-8f);
    }
    __syncthreads();

    // Phase 2: float2-vectorized normalize + residual + store. Rows 2*lane, 2*lane+1.
    const int row0 = 2 * lane;
    const float2 mu2 = *(const float2*)&smf[F_MU + row0];
    const float2 rs2 = *(const float2*)&smf[F_RSTD + row0];
    const size_t base = ((size_t)b * 512 * 256 + t) * 64;
#pragma unroll 4
    for (int i = 0; i < 32; ++i) {
        const int n = i * 16 + w;
        const float lw = smf[F_LW + n], lb = smf[F_LB + n];
        const float2 v2 = *(const float2*)&smf[F_STAGE + n * 68 + row0];
        const size_t gi = base + (size_t)n * 16384 + row0;
        const float2 xr = *(const float2*)(x + gi);
        float2 o2;
        o2.x = (v2.x - mu2.x) * rs2.x * lw + lb + xr.x;
        o2.y = (v2.y - mu2.y) * rs2.y * lw + lb + xr.y;
        *(float2*)(out + gi) = o2;
    }
}

// ---------------- launch ----------------

extern "C" void kernel_launch(void* const* d_in, const int* in_sizes, int n_in,
                              void* d_out, int out_size) {
    (void)in_sizes; (void)n_in; (void)out_size;
    const float* x      = (const float*)d_in[0];
    const float* s      = (const float*)d_in[1];
    // d_in[2..4]: prelu1_a, ln1_w, ln1_b — dead code in the reference
    const float* W      = (const float*)d_in[5];
    const float* bias   = (const float*)d_in[6];
    const float* prelu2 = (const float*)d_in[7];
    const float* ln2w   = (const float*)d_in[8];
    const float* ln2b   = (const float*)d_in[9];
    float* out = (float*)d_out;

    cudaFuncSetAttribute(fused_kernel,
                         cudaFuncAttributeMaxDynamicSharedMemorySize, SMEM_BYTES);

    prep_kernel<<<832, 256>>>(s, W, bias);
    fused_kernel<<<1024, 512, SMEM_BYTES>>>(x, prelu2, ln2w, ln2b, out);
}

// round 14
// speedup vs baseline: 1.0973x; 1.0244x over previous
#include <cuda_runtime.h>
#include <cuda_fp16.h>
#include <cstdint>

#define DEV_INLINE __device__ __forceinline__

constexpr int KTOT = 768;
constexpr int NSTAGES = 8, KSTAGE = 64;          // K = 512
constexpr int SBW = 36;                           // u32 words per B row (32 kt + 4 pad)
constexpr int SAW = 72;                           // u32 words per A k-row (64 m + 8 pad)
constexpr int B_STAGE_BYTES = 512 * SBW * 4;      // 73728
constexpr int B_HALF_BYTES  = B_STAGE_BYTES / 2;  // 36864 (n rows 0-255 / 256-511)
constexpr int A_STAGE_BYTES = 32 * SAW * 4;       // 9216

// static device scratch
__device__ float g_sbias[4 * 512];
__device__ __align__(128) uint32_t g_wst[NSTAGES * 512 * SBW];  // fp16-packed, padded W stages

// ---------------- PTX helpers ----------------

DEV_INLINE uint32_t smem_u32(const void* p) {
    uint32_t a;
    asm("{ .reg .u64 t; cvta.to.shared.u64 t, %1; cvt.u32.u64 %0, t; }" : "=r"(a) : "l"(p));
    return a;
}
DEV_INLINE void mbar_init(uint32_t a, uint32_t cnt) {
    asm volatile("mbarrier.init.shared.b64 [%0], %1;" :: "r"(a), "r"(cnt) : "memory");
}
DEV_INLINE void mbar_arrive(uint32_t a) {
    asm volatile("mbarrier.arrive.release.cta.shared::cta.b64 _, [%0];" :: "r"(a) : "memory");
}
DEV_INLINE void mbar_expect_tx(uint32_t a, uint32_t bytes) {
    asm volatile("mbarrier.arrive.expect_tx.shared.b64 _, [%0], %1;" :: "r"(a), "r"(bytes) : "memory");
}
DEV_INLINE void mbar_wait(uint32_t a, uint32_t parity) {
    asm volatile(
        "{ .reg .pred P;\n"
        "W_%=:\n"
        " mbarrier.try_wait.parity.acquire.cta.shared::cta.b64 P, [%0], %1, 0x989680;\n"
        " @P bra.uni D_%=;\n"
        " bra.uni W_%=;\n"
        "D_%=:\n}"
        :: "r"(a), "r"(parity) : "memory");
}
DEV_INLINE void bulk_g2s(uint32_t dst, const void* src, uint32_t bytes, uint32_t mbar) {
    asm volatile(
        "cp.async.bulk.shared::cluster.global.mbarrier::complete_tx::bytes [%0], [%1], %2, [%3];"
        :: "r"(dst), "l"(src), "r"(bytes), "r"(mbar) : "memory");
}
DEV_INLINE void mma_f16(float* d, const uint32_t* a, uint32_t b0, uint32_t b1) {
    asm volatile(
        "mma.sync.aligned.m16n8k16.row.col.f32.f16.f16.f32 "
        "{%0,%1,%2,%3}, {%4,%5,%6,%7}, {%8,%9}, {%0,%1,%2,%3};\n"
        : "+f"(d[0]), "+f"(d[1]), "+f"(d[2]), "+f"(d[3])
        : "r"(a[0]), "r"(a[1]), "r"(a[2]), "r"(a[3]), "r"(b0), "r"(b1));
}
DEV_INLINE void ldsm_x4(uint32_t& r0, uint32_t& r1, uint32_t& r2, uint32_t& r3, uint32_t addr) {
    asm volatile("ldmatrix.sync.aligned.m8n8.x4.shared.b16 {%0,%1,%2,%3}, [%4];"
                 : "=r"(r0), "=r"(r1), "=r"(r2), "=r"(r3) : "r"(addr));
}
DEV_INLINE uint32_t packh2(float lo, float hi) {
    __half2 h = __floats2half2_rn(lo, hi);
    return *reinterpret_cast<uint32_t*>(&h);
}

// ---------------- merged prologue kernel ----------------

__global__ void prep_kernel(const float* __restrict__ s,
                            const float* __restrict__ W,
                            const float* __restrict__ bias) {
    if (blockIdx.x < 576) {
        int idx = blockIdx.x * 256 + threadIdx.x;   // 8*512*36 = 147456
        if (idx >= NSTAGES * 512 * SBW) return;
        int kt = idx % SBW;
        int rest = idx / SBW;
        int n = rest & 511, st = rest >> 9;
        uint32_t v = 0;
        if (kt < 32) {
            const float* p = W + n * KTOT + st * KSTAGE + 2 * kt;
            v = packh2(p[0], p[1]);
        }
        g_wst[idx] = v;
    } else {
        int gw = ((blockIdx.x - 576) * 256 + threadIdx.x) >> 5;   // 2048 warps: (b,o)
        int lane = threadIdx.x & 31;
        int b = gw >> 9, o = gw & 511;
        const float* wrow = W + o * KTOT + 512;
        const float* srow = s + b * 256;
        float acc = 0.f;
#pragma unroll
        for (int j = 0; j < 8; ++j) acc += srow[lane + 32 * j] * wrow[lane + 32 * j];
#pragma unroll
        for (int off = 16; off; off >>= 1) acc += __shfl_xor_sync(0xffffffffu, acc, off);
        if (lane == 0) g_sbias[b * 512 + o] = acc + bias[o];
    }
}

// ---------------- fused kernel ----------------
// Grid 1024: CTA = (b,t). Tile 64(m) x 512(n), K=512 in 8 stages of 64.
// 512 threads = 16 warps (2m x 8n). Mbarrier-ring mainloop with B split in
// two n-halves: tma[2 buf][2 half] cnt1, rd[2][2] cnt8, ardy[4] cnt512.
// Warps wn<4 consume half0 (n<256); wn>=4 consume half1.

// smem layout (bytes / float indices)
constexpr int MB_TMA  = 0;                 // 4 x 8B: [buf][half]
constexpr int MB_ARDY = 32;                // 4 x 8B
constexpr int MB_RD   = 64;                // 4 x 8B: [buf][half]
constexpr int F_RS   = 24;                 // float indices (byte 96)
constexpr int F_RQ   = F_RS + 512;
constexpr int F_MU   = F_RQ + 512;
constexpr int F_RSTD = F_MU + 64;
constexpr int F_LW   = F_RSTD + 64;
constexpr int F_LB   = F_LW + 512;
constexpr int F_SBIA = F_LB + 512;         // ends float 2712
constexpr int SM_A   = 12288;              // 4 x 9216 = 36864
constexpr int SM_B   = SM_A + 4 * A_STAGE_BYTES;        // 49152
constexpr int SMEM_BYTES = SM_B + 2 * B_STAGE_BYTES;    // 196608
constexpr int F_STAGE = SM_A >> 2;         // epilogue staging [512 n][68]f over A+B region

__global__ __launch_bounds__(512, 1)
void fused_kernel(const float* __restrict__ x,
                  const float* __restrict__ prelu_a,
                  const float* __restrict__ lnw,
                  const float* __restrict__ lnb,
                  float* __restrict__ out) {
    extern __shared__ float smf[];
    const uint32_t smb = smem_u32(smf);
    const int tid = threadIdx.x;
    const int b = blockIdx.x >> 8;
    const int t = blockIdx.x & 255;

    // epilogue constants
    smf[F_LW + tid]   = lnw[tid];
    smf[F_LB + tid]   = lnb[tid];
    smf[F_SBIA + tid] = g_sbias[b * 512 + tid];

    if (tid == 0) {
#pragma unroll
        for (int i = 0; i < 4; ++i) mbar_init(smb + MB_TMA + 8 * i, 1);
#pragma unroll
        for (int i = 0; i < 4; ++i) mbar_init(smb + MB_ARDY + 8 * i, 512);
#pragma unroll
        for (int i = 0; i < 4; ++i) mbar_init(smb + MB_RD + 8 * i, 8);
    }
    __syncthreads();

    const int lane = tid & 31, w = tid >> 5;
    const int wm = w >> 3, wn = w & 7;
    const int half = wn >> 2;            // 0: n<256, 1: n>=256
    const int qid = lane >> 2, tig = lane & 3;
    const int akt = tid >> 4;            // 0..31  (k-pair row)
    const int am0 = (tid & 15) * 4;      // m quad

    const uint32_t b_lane_off =
        (uint32_t)((((lane >> 4) * 8 + (lane & 7)) * SBW + ((lane >> 3) & 1) * 4) * 4);

    const float* xa_base = x + (size_t)b * 512 * 16384 + t * 64 + am0;
    auto ldgA = [&](int s, float4& f0, float4& f1) {
        const float* p = xa_base + (size_t)(s * KSTAGE + 2 * akt) * 16384;
        f0 = *(const float4*)p;
        f1 = *(const float4*)(p + 16384);
    };
    auto stsA = [&](int abuf, const float4& f0, const float4& f1) {
        uint32_t w0 = packh2(f0.x, f1.x);
        uint32_t w1 = packh2(f0.y, f1.y);
        uint32_t w2 = packh2(f0.z, f1.z);
        uint32_t w3 = packh2(f0.w, f1.w);
        uint32_t dst = smb + SM_A + abuf * A_STAGE_BYTES + (akt * SAW + am0) * 4;
        asm volatile("st.shared.v4.b32 [%0], {%1,%2,%3,%4};"
                     :: "r"(dst), "r"(w0), "r"(w1), "r"(w2), "r"(w3));
    };

    float acc[2][8][4];
#pragma unroll
    for (int mt = 0; mt < 2; ++mt)
#pragma unroll
        for (int nt = 0; nt < 8; ++nt)
#pragma unroll
            for (int r = 0; r < 4; ++r) acc[mt][nt][r] = 0.f;

    // prologue: A stages 0,1 + B stages 0,1 (both halves)
    {
        float4 f0, f1;
        ldgA(0, f0, f1); stsA(0, f0, f1);
        mbar_arrive(smb + MB_ARDY + 0);
        ldgA(1, f0, f1); stsA(1, f0, f1);
        mbar_arrive(smb + MB_ARDY + 8);
    }
    if (tid == 0) {
#pragma unroll
        for (int i = 0; i < 4; ++i) {     // i = 2*buf + h
            const int bf = i >> 1, h = i & 1;
            mbar_expect_tx(smb + MB_TMA + 8 * i, B_HALF_BYTES);
            bulk_g2s(smb + SM_B + bf * B_STAGE_BYTES + h * B_HALF_BYTES,
                     g_wst + bf * 512 * SBW + h * (256 * SBW),
                     B_HALF_BYTES, smb + MB_TMA + 8 * i);
        }
    }

    float4 pf0, pf1;   // A prefetch registers
#pragma unroll 2
    for (int s = 0; s < NSTAGES; ++s) {
        const int buf = s & 1;
        const uint32_t par2 = (uint32_t)((s >> 1) & 1);   // tma / rd parity
        if (s + 2 < NSTAGES) ldgA(s + 2, pf0, pf1);

        mbar_wait(smb + MB_TMA + 16 * buf + 8 * half, par2);            // B(s) my half
        mbar_wait(smb + MB_ARDY + 8 * (s & 3), (uint32_t)((s >> 2) & 1)); // A(s) ready

        const uint32_t* A2 = (const uint32_t*)((const char*)smf + SM_A +
                                               (s & 3) * A_STAGE_BYTES);
        const uint32_t bwarp = smb + SM_B + buf * B_STAGE_BYTES +
                               (uint32_t)(wn * 64 * SBW * 4) + b_lane_off;

#pragma unroll
        for (int c4 = 0; c4 < 4; ++c4) {
            const int kt0 = c4 * 8;
            uint32_t bb[4][4];
#pragma unroll
            for (int np = 0; np < 4; ++np)
                ldsm_x4(bb[np][0], bb[np][1], bb[np][2], bb[np][3],
                        bwarp + (uint32_t)(np * 16 * SBW * 4 + kt0 * 4));
            uint32_t a[2][4];
#pragma unroll
            for (int mt = 0; mt < 2; ++mt) {
                const int m0 = wm * 32 + mt * 16 + qid;
                a[mt][0] = A2[(kt0 + tig) * SAW + m0];
                a[mt][1] = A2[(kt0 + tig) * SAW + m0 + 8];
                a[mt][2] = A2[(kt0 + 4 + tig) * SAW + m0];
                a[mt][3] = A2[(kt0 + 4 + tig) * SAW + m0 + 8];
            }
#pragma unroll
            for (int np = 0; np < 4; ++np) {
                mma_f16(acc[0][np * 2],     a[0], bb[np][0], bb[np][1]);
                mma_f16(acc[1][np * 2],     a[1], bb[np][0], bb[np][1]);
                mma_f16(acc[0][np * 2 + 1], a[0], bb[np][2], bb[np][3]);
                mma_f16(acc[1][np * 2 + 1], a[1], bb[np][2], bb[np][3]);
            }
        }

        // this warp done reading B(s) (its half) and A(s)
        if (lane == 0) mbar_arrive(smb + MB_RD + 16 * buf + 8 * half);

        if (s + 2 < NSTAGES) {
            stsA((s + 2) & 3, pf0, pf1);
            mbar_arrive(smb + MB_ARDY + 8 * ((s + 2) & 3));
            // two issuer warps per stage: w==s -> half0, w==s+8 -> half1
            if (lane == 0 && (w == s || w == s + 8)) {
                const int h = (w == s) ? 0 : 1;
                const uint32_t mbT = smb + MB_TMA + 16 * buf + 8 * h;
                mbar_wait(smb + MB_RD + 16 * buf + 8 * h, par2);  // 8 consumers done
                mbar_expect_tx(mbT, B_HALF_BYTES);
                bulk_g2s(smb + SM_B + buf * B_STAGE_BYTES + h * B_HALF_BYTES,
                         g_wst + (s + 2) * 512 * SBW + h * (256 * SBW),
                         B_HALF_BYTES, mbT);
            }
        }
    }

    __syncthreads();   // everyone done with mainloop; A+B region becomes staging

    // ---------------- epilogue ----------------
    const float pa = prelu_a[0];

    float srow[4] = {0.f, 0.f, 0.f, 0.f};
    float qrow[4] = {0.f, 0.f, 0.f, 0.f};
#pragma unroll
    for (int mt = 0; mt < 2; ++mt)
#pragma unroll
        for (int nt = 0; nt < 8; ++nt)
#pragma unroll
            for (int r = 0; r < 4; ++r) {
                const int hf = r >> 1;
                const int n = wn * 64 + nt * 8 + tig * 2 + (r & 1);
                const int rrow = wm * 32 + mt * 16 + hf * 8 + qid;
                float v = acc[mt][nt][r] + smf[F_SBIA + n];
                v = (v >= 0.f) ? v : pa * v;
                smf[F_STAGE + n * 68 + rrow] = v;   // stride 68: conflict-free
                srow[mt * 2 + hf] += v;
                qrow[mt * 2 + hf] += v * v;
            }
#pragma unroll
    for (int off = 1; off <= 2; off <<= 1)
#pragma unroll
        for (int i = 0; i < 4; ++i) {
            srow[i] += __shfl_xor_sync(0xffffffffu, srow[i], off);
            qrow[i] += __shfl_xor_sync(0xffffffffu, qrow[i], off);
        }
    if (tig == 0) {
#pragma unroll
        for (int i = 0; i < 4; ++i) {
            const int rrow = wm * 32 + (i >> 1) * 16 + (i & 1) * 8 + qid;
            smf[F_RS + rrow * 8 + wn] = srow[i];
            smf[F_RQ + rrow * 8 + wn] = qrow[i];
        }
    }
    __syncthreads();
    if (tid < 64) {
        float s8 = 0.f, q8 = 0.f;
#pragma unroll
        for (int j = 0; j < 8; ++j) {
            s8 += smf[F_RS + tid * 8 + j];
            q8 += smf[F_RQ + tid * 8 + j];
        }
        const float mu = s8 * (1.f / 512.f);
        float var = q8 * (1.f / 512.f) - mu * mu;
        var = fmaxf(var, 0.f);
        smf[F_MU + tid] = mu;
        smf[F_RSTD + tid] = rsqrtf(var + 1e-8f);
    }
    __syncthreads();

    // Phase 2: float2-vectorized normalize + residual + store. Rows 2*lane, 2*lane+1.
    const int row0 = 2 * lane;
    const float2 mu2 = *(const float2*)&smf[F_MU + row0];
    const float2 rs2 = *(const float2*)&smf[F_RSTD + row0];
    const size_t base = ((size_t)b * 512 * 256 + t) * 64;
#pragma unroll 4
    for (int i = 0; i < 32; ++i) {
        const int n = i * 16 + w;
        const float lw = smf[F_LW + n], lb = smf[F_LB + n];
        const float2 v2 = *(const float2*)&smf[F_STAGE + n * 68 + row0];
        const size_t gi = base + (size_t)n * 16384 + row0;
        const float2 xr = *(const float2*)(x + gi);
        float2 o2;
        o2.x = (v2.x - mu2.x) * rs2.x * lw + lb + xr.x;
        o2.y = (v2.y - mu2.y) * rs2.y * lw + lb + xr.y;
        *(float2*)(out + gi) = o2;
    }
}

// ---------------- launch ----------------

extern "C" void kernel_launch(void* const* d_in, const int* in_sizes, int n_in,
                              void* d_out, int out_size) {
    (void)in_sizes; (void)n_in; (void)out_size;
    const float* x      = (const float*)d_in[0];
    const float* s      = (const float*)d_in[1];
    // d_in[2..4]: prelu1_a, ln1_w, ln1_b — dead code in the reference
    const float* W      = (const float*)d_in[5];
    const float* bias   = (const float*)d_in[6];
    const float* prelu2 = (const float*)d_in[7];
    const float* ln2w   = (const float*)d_in[8];
    const float* ln2b   = (const float*)d_in[9];
    float* out = (float*)d_out;

    cudaFuncSetAttribute(fused_kernel,
                         cudaFuncAttributeMaxDynamicSharedMemorySize, SMEM_BYTES);

    prep_kernel<<<832, 256>>>(s, W, bias);
    fused_kernel<<<1024, 512, SMEM_BYTES>>>(x, prelu2, ln2w, ln2b, out);
}